// round 3
// baseline (speedup 1.0000x reference)
#include <cuda_runtime.h>

#define PP    35
#define CIN   7
#define C1    16
#define A1C   32
#define C2    64
#define A2C   128
#define C3    128
#define DD    10
#define HH    200
#define WWG   176
#define VMAX  20000
#define NBUCK 64
#define NCH   (C1 + C2 + C3)   // 208
#define NP1   20               // padded pair count for vfe1 (18 real)
#define NP2   18               // pair count for vfe2 (exact)
#define T2    288              // vfe2 threads (9 warps)
#define GRID2 296              // 2 CTAs/SM * 148

// ---------------- scratch ---------------------------------------------------------
__device__ float  g_h2[(size_t)VMAX * PP * C2];    // pre-BN h2
__device__ float  g_keep[(size_t)VMAX * PP];
__device__ float  g_max3[(size_t)VMAX * C3];
__device__ float  g_min3[(size_t)VMAX * C3];
__device__ double g_sumB [NBUCK][NCH];
__device__ double g_sqB  [NBUCK][NCH];
__device__ float  g_scale[NCH];
__device__ float  g_shift[NCH];

// ---------------- f32x2 helpers ----------------------------------------------------
__device__ __forceinline__ unsigned long long pack2(float lo, float hi) {
    unsigned long long r;
    asm("mov.b64 %0, {%1, %2};" : "=l"(r) : "f"(lo), "f"(hi));
    return r;
}
__device__ __forceinline__ float2 unpack2(unsigned long long v) {
    float2 r;
    asm("mov.b64 {%0, %1}, %2;" : "=f"(r.x), "=f"(r.y) : "l"(v));
    return r;
}
__device__ __forceinline__ void fma2(unsigned long long& d, unsigned long long a,
                                     unsigned long long b) {
    asm("fma.rn.f32x2 %0, %1, %2, %0;" : "+l"(d) : "l"(a), "l"(b));
}

// ---------------- zero stat buckets ------------------------------------------------
__global__ void k_zero_stats() {
    int n = NBUCK * NCH;
    for (int i = blockIdx.x * blockDim.x + threadIdx.x; i < n; i += gridDim.x * blockDim.x) {
        ((double*)g_sumB)[i] = 0.0;
        ((double*)g_sqB)[i]  = 0.0;
    }
}

// ---------------- pass 1: stats of h1 ---------------------------------------------
__global__ void k_stats1(const float* __restrict__ x,
                         const float* __restrict__ W1,
                         const float* __restrict__ b1, int V) {
    int N = V * PP;
    float lsum[C1], lsq[C1];
    #pragma unroll
    for (int u = 0; u < C1; u++) { lsum[u] = 0.f; lsq[u] = 0.f; }
    for (int r = blockIdx.x * blockDim.x + threadIdx.x; r < N; r += gridDim.x * blockDim.x) {
        float xv[CIN];
        #pragma unroll
        for (int c = 0; c < CIN; c++) xv[c] = x[(size_t)r * CIN + c];
        #pragma unroll
        for (int u = 0; u < C1; u++) {
            float h = b1[u];
            #pragma unroll
            for (int c = 0; c < CIN; c++) h = fmaf(xv[c], W1[c * C1 + u], h);
            lsum[u] += h; lsq[u] += h * h;
        }
    }
    __shared__ float ssum[C1], ssq[C1];
    if (threadIdx.x < C1) { ssum[threadIdx.x] = 0.f; ssq[threadIdx.x] = 0.f; }
    __syncthreads();
    #pragma unroll
    for (int u = 0; u < C1; u++) { atomicAdd(&ssum[u], lsum[u]); atomicAdd(&ssq[u], lsq[u]); }
    __syncthreads();
    if (threadIdx.x < C1) {
        int b = blockIdx.x & (NBUCK - 1);
        atomicAdd(&g_sumB[b][threadIdx.x], (double)ssum[threadIdx.x]);
        atomicAdd(&g_sqB [b][threadIdx.x], (double)ssq [threadIdx.x]);
    }
}

// ---------------- finalize BN params -----------------------------------------------
__global__ void k_finalize(const float* __restrict__ g, const float* __restrict__ be,
                           int off, int nc, double invN) {
    int u = threadIdx.x;
    if (u < nc) {
        double s = 0.0, q = 0.0;
        for (int b = 0; b < NBUCK; b++) { s += g_sumB[b][off + u]; q += g_sqB[b][off + u]; }
        double m   = s * invN;
        double var = q * invN - m * m;
        float  sc  = g[u] * rsqrtf((float)var + 1e-5f);
        g_scale[off + u] = sc;
        g_shift[off + u] = (float)((double)be[u] - m * (double)sc);
    }
}

// ---------------- pass 2: BN1+relu, max, concat; packed h2 GEMM -> g_h2 -----------
__global__ void __launch_bounds__(128) k_vfe1(const float* __restrict__ x,
                       const float* __restrict__ W1, const float* __restrict__ b1,
                       const float* __restrict__ W2, const float* __restrict__ b2, int V) {
    int v = blockIdx.x;
    if (v >= V) return;
    int t = threadIdx.x;

    __shared__ float  s_x[PP * CIN];
    __shared__ float  s_keep[PP + 1];
    __shared__ float  s_h1[PP * C1];
    __shared__ float  s_m1[C1];
    __shared__ float2 s_a1p[A1C * NP1];        // [k][pr], pr 0..19 (18 real)
    __shared__ float  s_w2[A1C * C2];
    __shared__ float  s_rs[4 * C2], s_rq[4 * C2];

    const float* xb = x + (size_t)v * (PP * CIN);
    for (int i = t; i < PP * CIN; i += 128) s_x[i] = xb[i];
    for (int i = t; i < A1C * C2; i += 128) s_w2[i] = W2[i];
    __syncthreads();

    if (t < PP) {
        float s = 0.f;
        #pragma unroll
        for (int c = 0; c < CIN; c++) s += s_x[t * CIN + c];
        float k = (s != 0.0f) ? 1.0f : 0.0f;
        s_keep[t] = k;
        g_keep[(size_t)v * PP + t] = k;
    }
    __syncthreads();

    for (int i = t; i < PP * C1; i += 128) {
        int p = i >> 4, u = i & 15;
        float h = b1[u];
        #pragma unroll
        for (int c = 0; c < CIN; c++) h = fmaf(s_x[p * CIN + c], W1[c * C1 + u], h);
        h = fmaf(h, g_scale[u], g_shift[u]);
        s_h1[i] = fmaxf(h, 0.0f);
    }
    __syncthreads();

    if (t < C1) {
        float m = s_h1[t];
        #pragma unroll 7
        for (int p = 1; p < PP; p++) m = fmaxf(m, s_h1[p * C1 + t]);
        s_m1[t] = m;
    }
    __syncthreads();

    for (int i = t; i < A1C * NP1; i += 128) {
        int k = i / NP1, pr = i % NP1;
        int p0 = 2 * pr, p1 = p0 + 1;
        float u0 = 0.f, u1 = 0.f;
        if (p0 < PP) u0 = (k < C1 ? s_h1[p0 * C1 + k] : s_m1[k - C1]) * s_keep[p0];
        if (p1 < PP) u1 = (k < C1 ? s_h1[p1 * C1 + k] : s_m1[k - C1]) * s_keep[p1];
        s_a1p[i] = make_float2(u0, u1);
    }
    __syncthreads();

    // GEMM: each thread 2 outputs x 5 pairs; 10 FFMA2 per k, 6 LDS per k
    int lane = t & 31, pg = t >> 5;        // pg 0..3
    int og = lane * 2;
    float b0 = b2[og], b1v = b2[og + 1];
    unsigned long long acc[5][2];
    #pragma unroll
    for (int n = 0; n < 5; n++) { acc[n][0] = pack2(b0, b0); acc[n][1] = pack2(b1v, b1v); }

    #pragma unroll 4
    for (int k = 0; k < A1C; k++) {
        float2 w = *(const float2*)&s_w2[k * C2 + og];
        unsigned long long w0 = pack2(w.x, w.x), w1 = pack2(w.y, w.y);
        const unsigned long long* ap = (const unsigned long long*)&s_a1p[k * NP1 + pg * 5];
        #pragma unroll
        for (int n = 0; n < 5; n++) {
            unsigned long long a = ap[n];
            fma2(acc[n][0], a, w0);
            fma2(acc[n][1], a, w1);
        }
    }

    float ls0 = 0.f, lq0 = 0.f, ls1 = 0.f, lq1 = 0.f;
    float* h2g = g_h2 + (size_t)v * (PP * C2);
    #pragma unroll
    for (int n = 0; n < 5; n++) {
        int pr = pg * 5 + n;
        if (pr < 18) {
            int p0 = 2 * pr, p1 = p0 + 1;
            float2 r0 = unpack2(acc[n][0]);
            float2 r1 = unpack2(acc[n][1]);
            *(float2*)&h2g[p0 * C2 + og] = make_float2(r0.x, r1.x);
            ls0 += r0.x; lq0 += r0.x * r0.x;
            ls1 += r1.x; lq1 += r1.x * r1.x;
            if (p1 < PP) {
                *(float2*)&h2g[p1 * C2 + og] = make_float2(r0.y, r1.y);
                ls0 += r0.y; lq0 += r0.y * r0.y;
                ls1 += r1.y; lq1 += r1.y * r1.y;
            }
        }
    }
    s_rs[pg * C2 + og] = ls0; s_rs[pg * C2 + og + 1] = ls1;
    s_rq[pg * C2 + og] = lq0; s_rq[pg * C2 + og + 1] = lq1;
    __syncthreads();
    if (t < C2) {
        float S = s_rs[t] + s_rs[C2 + t] + s_rs[2 * C2 + t] + s_rs[3 * C2 + t];
        float Q = s_rq[t] + s_rq[C2 + t] + s_rq[2 * C2 + t] + s_rq[3 * C2 + t];
        int b = v & (NBUCK - 1);
        atomicAdd(&g_sumB[b][C1 + t], (double)S);
        atomicAdd(&g_sqB [b][C1 + t], (double)Q);
    }
}

// ---------------- pass 3: persistent; Wd in shared; BN2+GEMM+stats+max/min --------
// dynamic smem layout (bytes):
//   [0, 65536)          s_wd   : Wd [128][128]
//   [65536, 83968)      s_a2p  : float2 [128][18]   (aliased by s_red after GEMM)
//   [65536, 83968)      s_red  : float [4][9][128]  (alias)
//   [83968, +8960)      s_hb   : float [35][64]
//   then s_m2[64], s_keep[36], s_sc[64], s_sh[64]
#define SM2_WD    0
#define SM2_A2P   65536
#define SM2_RED   65536
#define SM2_HB    83968
#define SM2_M2    (SM2_HB + PP * C2 * 4)
#define SM2_KEEP  (SM2_M2 + 64 * 4)
#define SM2_SC    (SM2_KEEP + 40 * 4)
#define SM2_SH    (SM2_SC + 64 * 4)
#define SM2_BYTES (SM2_SH + 64 * 4)

__global__ void __launch_bounds__(T2, 2) k_vfe2(const float4* __restrict__ Wd4,
                                                const float*  __restrict__ bd, int V) {
    extern __shared__ char sm2[];
    float*  s_wd   = (float*) (sm2 + SM2_WD);
    float2* s_a2p  = (float2*)(sm2 + SM2_A2P);
    float*  s_red  = (float*) (sm2 + SM2_RED);
    float*  s_hb   = (float*) (sm2 + SM2_HB);
    float*  s_m2   = (float*) (sm2 + SM2_M2);
    float*  s_keep = (float*) (sm2 + SM2_KEEP);
    float*  s_sc   = (float*) (sm2 + SM2_SC);
    float*  s_sh   = (float*) (sm2 + SM2_SH);

    int t = threadIdx.x;
    int lane = t & 31, wid = t >> 5;       // wid 0..8
    int og = lane * 4;

    // stage Wd + BN2 params once
    float4* s_wd4 = (float4*)s_wd;
    for (int i = t; i < (A2C * A2C) / 4; i += T2) s_wd4[i] = Wd4[i];
    if (t < C2) { s_sc[t] = g_scale[C1 + t]; s_sh[t] = g_shift[C1 + t]; }
    __syncthreads();

    float bq0 = bd[og], bq1 = bd[og + 1], bq2 = bd[og + 2], bq3 = bd[og + 3];

    for (int v = blockIdx.x; v < V; v += gridDim.x) {
        // ---- prep: h2 load + BN2 + relu ----
        const float4* h2g4 = (const float4*)(g_h2 + (size_t)v * (PP * C2));
        for (int i = t; i < (PP * C2) / 4; i += T2) {
            float4 h = h2g4[i];
            int u = (i & 15) * 4;
            h.x = fmaxf(fmaf(h.x, s_sc[u],     s_sh[u]),     0.f);
            h.y = fmaxf(fmaf(h.y, s_sc[u + 1], s_sh[u + 1]), 0.f);
            h.z = fmaxf(fmaf(h.z, s_sc[u + 2], s_sh[u + 2]), 0.f);
            h.w = fmaxf(fmaf(h.w, s_sc[u + 3], s_sh[u + 3]), 0.f);
            ((float4*)s_hb)[i] = h;
        }
        if (t < PP) s_keep[t] = g_keep[(size_t)v * PP + t];
        __syncthreads();

        if (t < C2) {
            float m = s_hb[t];
            #pragma unroll 7
            for (int p = 1; p < PP; p++) m = fmaxf(m, s_hb[p * C2 + t]);
            s_m2[t] = m;
        }
        __syncthreads();

        for (int i = t; i < A2C * NP2; i += T2) {
            int k = i / NP2, pr = i % NP2;
            int p0 = 2 * pr, p1 = p0 + 1;
            float u0 = (k < C2 ? s_hb[p0 * C2 + k] : s_m2[k - C2]) * s_keep[p0];
            float u1 = (p1 < PP) ?
                ((k < C2 ? s_hb[p1 * C2 + k] : s_m2[k - C2]) * s_keep[p1]) : 0.f;
            s_a2p[i] = make_float2(u0, u1);
        }
        __syncthreads();

        // ---- GEMM: thread = 4 outputs x 2 pairs; per k: 1 LDS.128 + 2 LDS.64 + 8 FFMA2
        unsigned long long acc[2][4];
        acc[0][0] = pack2(bq0, bq0); acc[0][1] = pack2(bq1, bq1);
        acc[0][2] = pack2(bq2, bq2); acc[0][3] = pack2(bq3, bq3);
        acc[1][0] = acc[0][0]; acc[1][1] = acc[0][1];
        acc[1][2] = acc[0][2]; acc[1][3] = acc[0][3];

        #pragma unroll 4
        for (int k = 0; k < A2C; k++) {
            float4 w = *(const float4*)&s_wd[k * A2C + og];
            unsigned long long w0 = pack2(w.x, w.x), w1 = pack2(w.y, w.y);
            unsigned long long w2 = pack2(w.z, w.z), w3 = pack2(w.w, w.w);
            const unsigned long long* ap =
                (const unsigned long long*)&s_a2p[k * NP2 + wid * 2];
            unsigned long long a0 = ap[0], a1 = ap[1];
            fma2(acc[0][0], a0, w0); fma2(acc[0][1], a0, w1);
            fma2(acc[0][2], a0, w2); fma2(acc[0][3], a0, w3);
            fma2(acc[1][0], a1, w0); fma2(acc[1][1], a1, w1);
            fma2(acc[1][2], a1, w2); fma2(acc[1][3], a1, w3);
        }
        __syncthreads();   // GEMM done; s_a2p region may be reused as s_red

        // ---- per-thread stats over its 2 pairs (exclude padded p=35) ----
        float ls[4] = {0, 0, 0, 0}, lq[4] = {0, 0, 0, 0};
        float lmx[4], lmn[4];
        #pragma unroll
        for (int q = 0; q < 4; q++) { lmx[q] = -3.4e38f; lmn[q] = 3.4e38f; }
        #pragma unroll
        for (int j = 0; j < 2; j++) {
            int pr = wid * 2 + j;
            bool has1 = (2 * pr + 1 < PP);
            #pragma unroll
            for (int q = 0; q < 4; q++) {
                float2 r = unpack2(acc[j][q]);
                ls[q] += r.x; lq[q] += r.x * r.x;
                lmx[q] = fmaxf(lmx[q], r.x); lmn[q] = fminf(lmn[q], r.x);
                if (has1) {
                    ls[q] += r.y; lq[q] += r.y * r.y;
                    lmx[q] = fmaxf(lmx[q], r.y); lmn[q] = fminf(lmn[q], r.y);
                }
            }
        }
        #pragma unroll
        for (int q = 0; q < 4; q++) {
            s_red[0 * 9 * 128 + wid * 128 + og + q] = ls[q];
            s_red[1 * 9 * 128 + wid * 128 + og + q] = lq[q];
            s_red[2 * 9 * 128 + wid * 128 + og + q] = lmx[q];
            s_red[3 * 9 * 128 + wid * 128 + og + q] = lmn[q];
        }
        __syncthreads();

        if (t < C3) {
            float S = 0.f, Q = 0.f, MX = -3.4e38f, MN = 3.4e38f;
            #pragma unroll
            for (int w = 0; w < 9; w++) {
                S += s_red[0 * 9 * 128 + w * 128 + t];
                Q += s_red[1 * 9 * 128 + w * 128 + t];
                MX = fmaxf(MX, s_red[2 * 9 * 128 + w * 128 + t]);
                MN = fminf(MN, s_red[3 * 9 * 128 + w * 128 + t]);
            }
            g_max3[(size_t)v * C3 + t] = MX;
            g_min3[(size_t)v * C3 + t] = MN;
            int b = v & (NBUCK - 1);
            atomicAdd(&g_sumB[b][C1 + C2 + t], (double)S);
            atomicAdd(&g_sqB [b][C1 + C2 + t], (double)Q);
        }
        __syncthreads();
    }
}

// ---------------- pass 4: BN3 + relu + max (via max/min) + scatter-add ------------
__global__ void k_scatter(const int* __restrict__ coord, float* __restrict__ out, int V) {
    int v = blockIdx.x;
    if (v >= V) return;
    int u = threadIdx.x;
    float sc = g_scale[C1 + C2 + u];
    float sh = g_shift[C1 + C2 + u];
    float h  = (sc >= 0.0f) ? g_max3[(size_t)v * C3 + u] : g_min3[(size_t)v * C3 + u];
    float val = fmaxf(fmaf(h, sc, sh), 0.0f);
    int cz = coord[v * 3 + 0];
    int cy = coord[v * 3 + 1];
    int cx = coord[v * 3 + 2];
    size_t off = (size_t)u * (DD * HH * WWG) + (size_t)cz * (HH * WWG) + (size_t)cy * WWG + cx;
    atomicAdd(out + off, val);
}

// ---------------- launch -----------------------------------------------------------
extern "C" void kernel_launch(void* const* d_in, const int* in_sizes, int n_in,
                              void* d_out, int out_size) {
    const float* x     = (const float*)d_in[0];
    const int*   coord = (const int*)  d_in[1];
    const float* W1 = (const float*)d_in[2];
    const float* b1 = (const float*)d_in[3];
    const float* g1 = (const float*)d_in[4];
    const float* be1= (const float*)d_in[5];
    const float* W2 = (const float*)d_in[6];
    const float* b2 = (const float*)d_in[7];
    const float* g2 = (const float*)d_in[8];
    const float* be2= (const float*)d_in[9];
    const float* Wd = (const float*)d_in[10];
    const float* bd = (const float*)d_in[11];
    const float* gd = (const float*)d_in[12];
    const float* bed= (const float*)d_in[13];

    int V = in_sizes[1] / 3;
    if (V > VMAX) V = VMAX;
    double invN = 1.0 / ((double)V * PP);

    static int smem_set = 0;
    if (!smem_set) {
        cudaFuncSetAttribute(k_vfe2, cudaFuncAttributeMaxDynamicSharedMemorySize, SM2_BYTES);
        smem_set = 1;
    }

    cudaMemsetAsync(d_out, 0, (size_t)out_size * sizeof(float), 0);
    k_zero_stats<<<32, 256>>>();
    k_stats1<<<592, 256>>>(x, W1, b1, V);
    k_finalize<<<1, 256>>>(g1, be1, 0, C1, invN);
    k_vfe1<<<V, 128>>>(x, W1, b1, W2, b2, V);
    k_finalize<<<1, 256>>>(g2, be2, C1, C2, invN);
    k_vfe2<<<GRID2, T2, SM2_BYTES>>>((const float4*)Wd, bd, V);
    k_finalize<<<1, 256>>>(gd, bed, C1 + C2, C3, invN);
    k_scatter<<<V, 128>>>(coord, (float*)d_out, V);
}